// round 15
// baseline (speedup 1.0000x reference)
#include <cuda_runtime.h>
#include <cstdint>
#include <cstddef>

// Problem shape (fixed by the reference setup_inputs)
#define BB 64
#define TT 2048
#define NN 32
#define KCH 8            // steps per super-step (chunk)
#define XCH 3            // transposed-tile ring chunks
#define NTH 256
#define KNINF (-1e4f)
#define NEG_BIG (-3.402823466e38f)
#define LSEG 128
#define MAXSEG (TT / LSEG)   // 16

// Transposed tile layout (per 4KB tile): column j at floats [j*32, j*32+32);
// 16B chunk c (i = 4c..4c+3) stored rotated at float offset ((c+j)&7)*4.
// -> LDS.128/STS.128 by lane j: 4-way conflict = minimal 4 wavefronts.

struct __align__(16) Smem {
    float x[XCH][KCH * NN * NN];      // 96KB folded (phi+tr), transposed tiles
    float rawT[2][3][2 * NN * NN];    // 48KB raw rings: [Twarp][slot][2 tiles]
    float aring[32][NN];              // 4KB alpha ring, slot = t & 31
    unsigned char back[TT][NN];       // 64KB backpointers
    unsigned char M[MAXSEG][NN];      // composed segment maps
    int entry[MAXSEG];
    int misc[16];                     // [0..7] warp counts, [8] last_tag
};

__device__ __forceinline__ void cp16(unsigned dst, const void* src) {
    asm volatile("cp.async.cg.shared.global [%0], [%1], 16;" :: "r"(dst), "l"(src));
}
__device__ __forceinline__ void cp_commit() { asm volatile("cp.async.commit_group;"); }
template<int Nn> __device__ __forceinline__ void cp_wait() {
    asm volatile("cp.async.wait_group %0;" :: "n"(Nn));
}

__global__ void __launch_bounds__(NTH, 1)
viterbi_kernel(const float* __restrict__ lp, const int* __restrict__ mask,
               const int* __restrict__ startc, const int* __restrict__ endc,
               const int* __restrict__ transc, float* __restrict__ out)
{
    extern __shared__ __align__(16) char smraw[];
    Smem& sm = *reinterpret_cast<Smem*>(smraw);
    const int b    = blockIdx.x;
    const int tid  = threadIdx.x;
    const int w    = tid >> 5;
    const int lane = tid & 31;

    // ---- sequence length (mask is prefix-true) ----
    int cnt = 0;
    #pragma unroll
    for (int t = tid; t < TT; t += NTH) cnt += (mask[b * TT + t] != 0);
    #pragma unroll
    for (int o = 16; o; o >>= 1) cnt += __shfl_xor_sync(0xffffffffu, cnt, o);
    if (lane == 0) sm.misc[w] = cnt;
    __syncthreads();
    int len = 0;
    #pragma unroll
    for (int q = 0; q < 8; q++) len += sm.misc[q];
    const int last = len - 1;

    const float* lpb = lp + (size_t)b * TT * NN * NN;
    const int SSMAX = last / KCH + 2;

    if (w == 0) {
        // ================= alpha warp (SMSP0, solo): lane = column j =================
        const int j = lane;
        const float sp_j = startc[j] ? 0.0f : KNINF;
        const float ep_j = endc[j]   ? 0.0f : KNINF;

        // t = 0 from gmem (raw phi, coalesced per-i): alpha0 = max_i phi0[i][j] + sp (+ep)
        float bv = NEG_BIG;
        #pragma unroll
        for (int i = 0; i < NN; i++) bv = fmaxf(bv, __ldg(lpb + i * NN + j));
        sm.aring[0][j] = (bv + sp_j) + ((last == 0) ? ep_j : 0.0f);

        for (int ss = 0; ss < SSMAX; ss++) {
            __syncthreads();                    // x chunk ss ready; aring visible
            int tlo = (ss == 0) ? 1 : (KCH * ss);
            int thi = min(last, KCH * ss + KCH - 1);
            if (tlo > thi) continue;
            const float* xch = sm.x[ss % XCH];
            const bool haveEnd = (thi == last);
            const int thiN = haveEnd ? thi - 1 : thi;

            for (int t = tlo; t <= thiN; t++) {   // normal steps: s = (phi+tr) + a
                const float* tcol = xch + ((t & 7) << 10) + (j << 5);
                const float* ar = sm.aring[(t - 1) & 31];
                float s[NN];
                #pragma unroll
                for (int c = 0; c < 8; c++) {
                    float4 tv = *reinterpret_cast<const float4*>(tcol + (((c + j) & 7) << 2));
                    float4 av = *reinterpret_cast<const float4*>(ar + (c << 2));
                    s[4*c+0] = tv.x + av.x;  s[4*c+1] = tv.y + av.y;
                    s[4*c+2] = tv.z + av.z;  s[4*c+3] = tv.w + av.w;
                }
                #pragma unroll
                for (int off = 1; off < NN; off <<= 1)
                    #pragma unroll
                    for (int i = 0; i < NN; i += 2 * off)
                        s[i] = fmaxf(s[i], s[i + off]);
                sm.aring[t & 31][j] = s[0];
                __syncwarp();
            }
            if (haveEnd) {                       // peeled end step: ((phi+tr)+ep)+a
                const int t = last;
                const float* tcol = xch + ((t & 7) << 10) + (j << 5);
                const float* ar = sm.aring[(t - 1) & 31];
                float s[NN];
                #pragma unroll
                for (int c = 0; c < 8; c++) {
                    float4 tv = *reinterpret_cast<const float4*>(tcol + (((c + j) & 7) << 2));
                    float4 av = *reinterpret_cast<const float4*>(ar + (c << 2));
                    s[4*c+0] = (tv.x + ep_j) + av.x;  s[4*c+1] = (tv.y + ep_j) + av.y;
                    s[4*c+2] = (tv.z + ep_j) + av.z;  s[4*c+3] = (tv.w + ep_j) + av.w;
                }
                #pragma unroll
                for (int off = 1; off < NN; off <<= 1)
                    #pragma unroll
                    for (int i = 0; i < NN; i += 2 * off)
                        s[i] = fmaxf(s[i], s[i + off]);
                sm.aring[t & 31][j] = s[0];
                __syncwarp();
            }
        }
    } else if (w == 1 || w == 2) {
        // ===== transpose+fold producers (SMSP1/2, solo). w1: tiles %8 in 0..3; w2: 4..7 =====
        const int j = lane;
        const int woff = w - 1;                 // 0 or 1
        const int tileOff = woff * 4;
        float trv[NN];
        #pragma unroll
        for (int i = 0; i < NN; i++)
            trv[i] = transc[i * NN + j] ? 0.0f : KNINF;
        const unsigned rawBase = (unsigned)__cvta_generic_to_shared(&sm.rawT[0][0][0])
                                 + (unsigned)(woff * 24576);

        auto issue = [&](int g) {               // 2-tile group g -> raw slot g%3
            #pragma unroll
            for (int r = 0; r < 16; r++) {
                int cid = lane + 32 * r;        // 0..511 chunks
                int u = cid >> 8, within = cid & 255;
                int ri = within >> 3, c = within & 7;
                int t_g = 8 * (g >> 1) + 2 * (g & 1) + u + tileOff;
                if (t_g <= last) {
                    unsigned dst = rawBase + (unsigned)((g % 3) * 8192 + u * 4096
                                   + ri * 128 + ((c * 16) ^ ((ri & 16) ? 64 : 0)));
                    cp16(dst, lpb + (size_t)t_g * (NN * NN) + ri * NN + c * 4);
                }
            }
            cp_commit();
        };
        auto xpose = [&](int g) {               // fold tr, write transposed
            #pragma unroll
            for (int u = 0; u < 2; u++) {
                int t_g = 8 * (g >> 1) + 2 * (g & 1) + u + tileOff;
                if (t_g >= 1 && t_g <= last) {
                    const float* rw = sm.rawT[woff][g % 3] + u * (NN * NN);
                    float tv[NN];
                    #pragma unroll
                    for (int i = 0; i < NN; i++)
                        tv[i] = rw[i * NN + (j ^ (i & 16))] + trv[i];
                    float* dc = sm.x[(t_g >> 3) % XCH] + ((t_g & 7) << 10) + (j << 5);
                    #pragma unroll
                    for (int c = 0; c < 8; c++)
                        *reinterpret_cast<float4*>(dc + (((c + j) & 7) << 2)) =
                            make_float4(tv[4*c], tv[4*c+1], tv[4*c+2], tv[4*c+3]);
                }
            }
        };

        // prologue: chunk 0 (groups 0,1); keep 1 chunk of lookahead in raw ring
        issue(0); issue(1); issue(2);
        cp_wait<2>(); __syncwarp(); xpose(0);
        issue(3);
        cp_wait<2>(); __syncwarp(); xpose(1);
        __syncwarp();
        for (int ss = 0; ss < SSMAX; ss++) {
            __syncthreads();
            issue(2 * ss + 4);
            cp_wait<2>(); __syncwarp(); xpose(2 * ss + 2);   // chunk ss+1, 1st half
            __syncwarp();
            issue(2 * ss + 5);
            cp_wait<2>(); __syncwarp(); xpose(2 * ss + 3);   // chunk ss+1, 2nd half
            __syncwarp();
        }
        cp_wait<0>();
    } else if (w == 3 || w == 7) {
        // ===== backpointer warps (SMSP3): 16 columns each, 2 lanes/column =====
        const int j    = ((w == 3) ? 0 : 16) + (lane & 15);
        const int half = lane >> 4;             // i in [16*half, 16*half+16)
        const float ep_j = endc[j] ? 0.0f : KNINF;

        for (int ss = 0; ss < SSMAX; ss++) {
            __syncthreads();
            if (ss < 1) continue;
            int tlo = max(1, (ss - 1) * KCH);
            int thi = min(last, (ss - 1) * KCH + KCH - 1);
            if (tlo > thi) continue;
            const float* xch = sm.x[(ss - 1) % XCH];
            for (int t = tlo; t <= thi; t++) {
                const float* tcol = xch + ((t & 7) << 10) + (j << 5);
                const float* ar = sm.aring[(t - 1) & 31];
                float sv[16];
                if (t != last) {
                    #pragma unroll
                    for (int cc = 0; cc < 4; cc++) {
                        int c = 4 * half + cc;
                        float4 tv = *reinterpret_cast<const float4*>(tcol + (((c + j) & 7) << 2));
                        float4 av = *reinterpret_cast<const float4*>(ar + (c << 2));
                        sv[4*cc+0] = tv.x + av.x;  sv[4*cc+1] = tv.y + av.y;
                        sv[4*cc+2] = tv.z + av.z;  sv[4*cc+3] = tv.w + av.w;
                    }
                } else {
                    #pragma unroll
                    for (int cc = 0; cc < 4; cc++) {
                        int c = 4 * half + cc;
                        float4 tv = *reinterpret_cast<const float4*>(tcol + (((c + j) & 7) << 2));
                        float4 av = *reinterpret_cast<const float4*>(ar + (c << 2));
                        sv[4*cc+0] = (tv.x + ep_j) + av.x;  sv[4*cc+1] = (tv.y + ep_j) + av.y;
                        sv[4*cc+2] = (tv.z + ep_j) + av.z;  sv[4*cc+3] = (tv.w + ep_j) + av.w;
                    }
                }
                float m[16];
                #pragma unroll
                for (int k = 0; k < 16; k++) m[k] = sv[k];
                #pragma unroll
                for (int off = 1; off < 16; off <<= 1)
                    #pragma unroll
                    for (int k = 0; k < 16; k += 2 * off)
                        m[k] = fmaxf(m[k], m[k + off]);
                const float lm = m[0];
                int idx = 15;
                #pragma unroll
                for (int k = 14; k >= 0; k--)
                    if (sv[k] == lm) idx = k;             // first-max within half
                int gi = half * 16 + idx;
                float olm = __shfl_xor_sync(0xffffffffu, lm, 16);
                int   ogi = __shfl_xor_sync(0xffffffffu, gi, 16);
                int res = (olm > lm) ? ogi : gi;          // tie -> half0 (smaller i)
                if (half == 0) sm.back[t][j] = (unsigned char)res;
            }
        }
    } else {
        // idle warps: barrier keepers (w4, w5, w6)
        for (int ss = 0; ss < SSMAX; ss++) __syncthreads();
    }

    __syncthreads();   // alpha[last], back[] all published

    // ---- final max / argmax over tags (first occurrence) ----
    if (w == 0) {
        float v  = sm.aring[last & 31][lane];
        int  idx = lane;
        #pragma unroll
        for (int o = 16; o; o >>= 1) {
            float ov = __shfl_xor_sync(0xffffffffu, v, o);
            int   oi = __shfl_xor_sync(0xffffffffu, idx, o);
            if (ov > v || (ov == v && oi < idx)) { v = ov; idx = oi; }
        }
        if (lane == 0) { out[b] = v; sm.misc[8] = idx; }
    }
    __syncthreads();
    const int last_tag = sm.misc[8];

    float* tags = out + BB + (size_t)b * TT;
    for (int t = len + tid; t < TT; t += NTH) tags[t] = -1.0f;   // PADDING_INDEX

    if (last == 0) {
        if (tid == 0) tags[0] = (float)last_tag;
        return;
    }

    // ---- parallel backtrack: segment-composed pointer chase ----
    const int nseg = (last + LSEG - 1) / LSEG;
    for (int q = tid; q < nseg * NN; q += NTH) {
        const int s  = q >> 5;
        int y        = q & 31;
        const int lo = s * LSEG;
        const int hi = min((s + 1) * LSEG, last);
        for (int t = hi; t > lo; t--) y = sm.back[t][y];
        sm.M[s][q & 31] = (unsigned char)y;
    }
    __syncthreads();
    if (tid == 0) {
        int cur = last_tag;
        sm.entry[nseg - 1] = cur;
        for (int s = nseg - 1; s >= 1; s--) {
            cur = sm.M[s][cur];
            sm.entry[s - 1] = cur;
        }
        tags[0] = (float)sm.M[0][cur];
    }
    __syncthreads();
    if (tid < nseg) {
        const int s  = tid;
        const int lo = s * LSEG;
        const int hi = min((s + 1) * LSEG, last);
        int cur = sm.entry[s];
        for (int t = hi; t > lo; t--) {
            tags[t] = (float)cur;
            cur = sm.back[t][cur];
        }
    }
}

extern "C" void kernel_launch(void* const* d_in, const int* in_sizes, int n_in,
                              void* d_out, int out_size)
{
    const float* lp   = (const float*)d_in[0];
    const int* mask   = (const int*)d_in[1];
    const int* startc = (const int*)d_in[2];
    const int* endc   = (const int*)d_in[3];
    const int* transc = (const int*)d_in[4];
    float* out = (float*)d_out;
    (void)in_sizes; (void)n_in; (void)out_size;

    const int smem_bytes = (int)sizeof(Smem);   // ~213 KB (< 227 KB limit)
    cudaFuncSetAttribute(viterbi_kernel,
                         cudaFuncAttributeMaxDynamicSharedMemorySize, smem_bytes);
    viterbi_kernel<<<BB, NTH, smem_bytes>>>(lp, mask, startc, endc, transc, out);
}